// round 7
// baseline (speedup 1.0000x reference)
#include <cuda_runtime.h>
#include <cstdint>

#define Bn 8
#define Ln 2500
#define Dn 512
#define Yn 8921
#define YT 128          // y per CTA
#define LT 64           // l per CTA tile
#define KC 128          // k (int8 bytes) per chunk
#define NCH 4           // 512 / 128
#define NTILES 40       // ceil(2500/64)
#define NT 256
#define ROWB 144                    // smem row stride bytes (128 data + 16 pad)
#define T128 (128 * ROWB)           // 18432 (U/F tiles, 128 rows)
#define T64  (64 * ROWB)            // 9216  (X tiles, 64 rows)
#define OFF_UH 0
#define OFF_UL T128
#define OFF_FH (2 * T128)
#define OFF_FL (3 * T128)
#define OFF_XH (4 * T128)
#define OFF_XL (4 * T128 + T64)
#define BUFB (4 * T128 + 2 * T64)   // 92160
#define SMEM_BYTES (2 * BUFB)       // 184320

// int8 hi/lo scratch + per-row scales (device globals; no runtime alloc)
__device__ int8_t g_uh8[(size_t)Yn * Dn];
__device__ int8_t g_ul8[(size_t)Yn * Dn];
__device__ int8_t g_fh8[(size_t)Yn * Dn];
__device__ int8_t g_fl8[(size_t)Yn * Dn];
__device__ int8_t g_xh8[(size_t)Bn * Ln * Dn];
__device__ int8_t g_xl8[(size_t)Bn * Ln * Dn];
__device__ float  g_su[Yn];
__device__ float  g_sf[Yn];
__device__ float  g_sx[(size_t)Bn * Ln];

// mma.sync m16n8k32 s8 with exact s32 accumulate (plain sm_80+ instruction)
#define MMAS8(D, A, B)                                                      \
    asm volatile(                                                           \
        "mma.sync.aligned.m16n8k32.row.col.s32.s8.s8.s32 "                  \
        "{%0,%1,%2,%3}, {%4,%5,%6,%7}, {%8,%9}, {%0,%1,%2,%3};"             \
        : "+r"((D)[0]), "+r"((D)[1]), "+r"((D)[2]), "+r"((D)[3])            \
        : "r"((A)[0]), "r"((A)[1]), "r"((A)[2]), "r"((A)[3]),               \
          "r"((B)[0]), "r"((B)[1]))

#define LDSM4(R0, R1, R2, R3, addr)                                         \
    asm volatile(                                                           \
        "ldmatrix.sync.aligned.m8n8.x4.shared.b16 {%0,%1,%2,%3}, [%4];"     \
        : "=r"(R0), "=r"(R1), "=r"(R2), "=r"(R3) : "r"(addr))

static __device__ __forceinline__ void cp16(uint32_t dst, const void* src,
                                            bool v) {
    int sz = v ? 16 : 0;   // sz=0 -> zero-fill 16B, no gmem read
    asm volatile("cp.async.cg.shared.global [%0], [%1], 16, %2;"
                 :: "r"(dst), "l"(src), "r"(sz));
}
template <int N>
static __device__ __forceinline__ void cpwait() {
    asm volatile("cp.async.wait_group %0;" :: "n"(N) : "memory");
}
static __device__ __forceinline__ uint32_t smem_u32(const void* p) {
    uint32_t a;
    asm("{ .reg .u64 t; cvta.to.shared.u64 t, %1; cvt.u32.u64 %0, t; }"
        : "=r"(a) : "l"(p));
    return a;
}

// stage one k-chunk: 4 W tiles [128 x 128 int8] + 2 X tiles [64 x 128 int8]
static __device__ __forceinline__ void stage_chunk(
    uint32_t bufaddr, int tid, int b, int y0, int l0, int k0)
{
    const int8_t* w[4] = {
        g_uh8 + (size_t)y0 * Dn, g_ul8 + (size_t)y0 * Dn,
        g_fh8 + (size_t)y0 * Dn, g_fl8 + (size_t)y0 * Dn };
    const int limW = Yn - y0;
#pragma unroll
    for (int sub = 0; sub < 4; sub++) {
#pragma unroll
        for (int j = 0; j < 4; j++) {
            int idx = tid + j * NT;              // 0..1023 = 128 rows x 8 segs
            int r = idx >> 3, seg = idx & 7;
            cp16(bufaddr + sub * T128 + (uint32_t)(r * ROWB + seg * 16),
                 w[sub] + (size_t)r * Dn + k0 + seg * 16, r < limW);
        }
    }
    const int8_t* xh = g_xh8 + ((size_t)b * Ln + l0) * Dn;
    const int8_t* xl = g_xl8 + ((size_t)b * Ln + l0) * Dn;
    const int limX = Ln - l0;
#pragma unroll
    for (int j = 0; j < 2; j++) {
        int idx = tid + j * NT;                  // 0..511 = 64 rows x 8 segs
        int r = idx >> 3, seg = idx & 7;
        uint32_t doff = (uint32_t)(r * ROWB + seg * 16);
        cp16(bufaddr + OFF_XH + doff, xh + (size_t)r * Dn + k0 + seg * 16, r < limX);
        cp16(bufaddr + OFF_XL + doff, xl + (size_t)r * Dn + k0 + seg * 16, r < limX);
    }
    asm volatile("cp.async.commit_group;" ::: "memory");
}

__global__ __launch_bounds__(NT)
void attn_mma_kernel(const float* __restrict__ f_b, float* __restrict__ out)
{
    extern __shared__ float smem[];
    const uint32_t sbase = smem_u32(smem);
    const int tid  = threadIdx.x;
    const int lane = tid & 31;
    const int g    = lane >> 2;          // group id 0..7
    const int tg   = lane & 3;           // thread in group 0..3
    const int wid  = tid >> 5;
    const int wy   = wid >> 1;           // warp y index 0..3 (32 y each)
    const int wl   = wid & 1;            // warp l index 0..1 (32 l each)
    const int b    = blockIdx.y;
    const int y0   = blockIdx.x * YT;

    // ldmatrix per-lane address components (bytes) — identical to bf16 version
    const int quad = lane >> 3, r8 = lane & 7;
    const uint32_t laneA = (uint32_t)((r8 + (quad & 1) * 8) * ROWB + (quad >> 1) * 16);
    const uint32_t laneB = (uint32_t)((r8 + (quad >> 1) * 8) * ROWB + (quad & 1) * 16);
    uint32_t aRow[2], bRow[2];
#pragma unroll
    for (int a = 0; a < 2; a++)  aRow[a]  = (uint32_t)((wy * 32 + a * 16) * ROWB) + laneA;
#pragma unroll
    for (int cp = 0; cp < 2; cp++) bRow[cp] = (uint32_t)((wl * 32 + cp * 16) * ROWB) + laneB;

    // per-row scales for this thread's y rows (zero-padded tail masked at output)
    float su[2][2], sf[2][2];
#pragma unroll
    for (int a = 0; a < 2; a++)
#pragma unroll
        for (int p = 0; p < 2; p++) {
            int yg = y0 + wy * 32 + a * 16 + p * 8 + g;
            su[a][p] = (yg < Yn) ? g_su[yg] : 0.f;
            sf[a][p] = (yg < Yn) ? g_sf[yg] : 0.f;
        }

    // running softmax sums for this thread's 4 y rows
    float ss[4] = {0.f, 0.f, 0.f, 0.f};
    float zz[4] = {0.f, 0.f, 0.f, 0.f};

    stage_chunk(sbase, tid, b, y0, 0, 0);   // tile 0, chunk 0 -> buf 0

    for (int t = 0; t < NTILES; t++) {
        const int l0 = t * LT;

        int dShh[2][4][4], dSm[2][4][4], dThh[2][4][4], dTm[2][4][4];
#pragma unroll
        for (int a = 0; a < 2; a++)
#pragma unroll
            for (int c = 0; c < 4; c++)
#pragma unroll
                for (int r = 0; r < 4; r++) {
                    dShh[a][c][r] = 0; dSm[a][c][r] = 0;
                    dThh[a][c][r] = 0; dTm[a][c][r] = 0;
                }

        for (int ch = 0; ch < NCH; ch++) {
            const bool last_all = (t == NTILES - 1) && (ch == NCH - 1);
            if (!last_all) {
                int nl0 = (ch == NCH - 1) ? l0 + LT : l0;
                int nk0 = (ch == NCH - 1) ? 0 : (ch + 1) * KC;
                stage_chunk(sbase + ((ch + 1) & 1) * BUFB, tid, b, y0, nl0, nk0);
                cpwait<1>();
            } else {
                cpwait<0>();
            }
            __syncthreads();

            const uint32_t bufb = sbase + (ch & 1) * BUFB;

#pragma unroll
            for (int ka = 0; ka < 4; ka++) {        // four k32 steps
                const uint32_t kao = (uint32_t)(ka * 32);
                uint32_t uh[2][4], ul[2][4], fh[2][4], fl[2][4];
#pragma unroll
                for (int a = 0; a < 2; a++) {
                    uint32_t ab = bufb + aRow[a] + kao;
                    LDSM4(uh[a][0], uh[a][1], uh[a][2], uh[a][3], ab + OFF_UH);
                    LDSM4(ul[a][0], ul[a][1], ul[a][2], ul[a][3], ab + OFF_UL);
                    LDSM4(fh[a][0], fh[a][1], fh[a][2], fh[a][3], ab + OFF_FH);
                    LDSM4(fl[a][0], fl[a][1], fl[a][2], fl[a][3], ab + OFF_FL);
                }
                uint32_t bh[4][2], bl[4][2];
#pragma unroll
                for (int cp = 0; cp < 2; cp++) {
                    uint32_t bb = bufb + bRow[cp] + kao;
                    LDSM4(bh[2*cp][0], bh[2*cp][1], bh[2*cp+1][0], bh[2*cp+1][1],
                          bb + OFF_XH);
                    LDSM4(bl[2*cp][0], bl[2*cp][1], bl[2*cp+1][0], bl[2*cp+1][1],
                          bb + OFF_XL);
                }
#pragma unroll
                for (int a = 0; a < 2; a++) {
#pragma unroll
                    for (int c = 0; c < 4; c++) {
                        // S: hh exact; (hl + lh) share one accumulator
                        MMAS8(dShh[a][c], uh[a], bh[c]);
                        MMAS8(dSm[a][c],  uh[a], bl[c]);
                        MMAS8(dSm[a][c],  ul[a], bh[c]);
                        MMAS8(dThh[a][c], fh[a], bh[c]);
                        MMAS8(dTm[a][c],  fh[a], bl[c]);
                        MMAS8(dTm[a][c],  fl[a], bh[c]);
                    }
                }
            }
            __syncthreads();   // release buf (ch&1) for the stage at iter ch+1
        }

        // epilogue: dequant + exp + weighted accumulate (regs only)
        const float C = 1.0f / 254.0f;
#pragma unroll
        for (int a = 0; a < 2; a++)
#pragma unroll
            for (int c = 0; c < 4; c++) {
                int le = l0 + wl * 32 + c * 8 + 2 * tg;
                float sx0 = (le     < Ln) ? g_sx[(size_t)b * Ln + le]     : 0.f;
                float sx1 = (le + 1 < Ln) ? g_sx[(size_t)b * Ln + le + 1] : 0.f;
#pragma unroll
                for (int p = 0; p < 2; p++) {
                    float S0 = su[a][p] * sx0 *
                               ((float)dShh[a][c][2*p]   + (float)dSm[a][c][2*p]   * C);
                    float T0 = sf[a][p] * sx0 *
                               ((float)dThh[a][c][2*p]   + (float)dTm[a][c][2*p]   * C);
                    float S1 = su[a][p] * sx1 *
                               ((float)dShh[a][c][2*p+1] + (float)dSm[a][c][2*p+1] * C);
                    float T1 = sf[a][p] * sx1 *
                               ((float)dThh[a][c][2*p+1] + (float)dTm[a][c][2*p+1] * C);
                    if (le < Ln)     { float e = __expf(S0); ss[a*2+p] += e; zz[a*2+p] += e * T0; }
                    if (le + 1 < Ln) { float e = __expf(S1); ss[a*2+p] += e; zz[a*2+p] += e * T1; }
                }
            }
    }

    // reduce across the 4 lanes sharing each y row (tg dimension)
#pragma unroll
    for (int i = 0; i < 4; i++) {
        ss[i] += __shfl_xor_sync(0xffffffffu, ss[i], 1);
        ss[i] += __shfl_xor_sync(0xffffffffu, ss[i], 2);
        zz[i] += __shfl_xor_sync(0xffffffffu, zz[i], 1);
        zz[i] += __shfl_xor_sync(0xffffffffu, zz[i], 2);
    }

    // cross-warp (wl) reduction via smem (all staging finished by now)
    __syncthreads();
    float* sred = smem;          // [2][128]
    float* zred = smem + 256;    // [2][128]
    if (tg == 0) {
#pragma unroll
        for (int i = 0; i < 4; i++) {
            int yl = wy * 32 + (i >> 1) * 16 + (i & 1) * 8 + g;
            sred[wl * 128 + yl] = ss[i];
            zred[wl * 128 + yl] = zz[i];
        }
    }
    __syncthreads();
    if (tid < 128) {
        int yg = y0 + tid;
        if (yg < Yn) {
            float s = sred[tid] + sred[128 + tid];
            float z = zred[tid] + zred[128 + tid];
            out[(size_t)b * Yn + yg] = z / s + f_b[yg];
        }
    }
}

// ---------- prepass: fp32 rows -> int8 hi/lo + per-row scale ----------
__global__ void quant_rows(const float* __restrict__ src, int8_t* __restrict__ hi,
                           int8_t* __restrict__ lo, float* __restrict__ sc,
                           int nrows)
{
    int row = blockIdx.x * (blockDim.x >> 5) + (threadIdx.x >> 5);
    if (row >= nrows) return;
    int lane = threadIdx.x & 31;
    const float4* s4 = (const float4*)(src + (size_t)row * Dn);
    float4 v[4];
    float m = 0.f;
#pragma unroll
    for (int j = 0; j < 4; j++) {
        v[j] = s4[lane + j * 32];
        m = fmaxf(m, fmaxf(fmaxf(fabsf(v[j].x), fabsf(v[j].y)),
                           fmaxf(fabsf(v[j].z), fabsf(v[j].w))));
    }
#pragma unroll
    for (int o = 16; o; o >>= 1) m = fmaxf(m, __shfl_xor_sync(0xffffffffu, m, o));
    float inv = (m > 0.f) ? 127.f / m : 0.f;
    if (lane == 0) sc[row] = m * (1.0f / 127.0f);
    char4* h4p = (char4*)(hi + (size_t)row * Dn);
    char4* l4p = (char4*)(lo + (size_t)row * Dn);
#pragma unroll
    for (int j = 0; j < 4; j++) {
        float q[4] = {v[j].x * inv, v[j].y * inv, v[j].z * inv, v[j].w * inv};
        char hc[4], lc[4];
#pragma unroll
        for (int e = 0; e < 4; e++) {
            float h = rintf(q[e]);
            hc[e] = (char)(int)h;
            lc[e] = (char)(int)rintf((q[e] - h) * 254.f);
        }
        h4p[lane + j * 32] = make_char4(hc[0], hc[1], hc[2], hc[3]);
        l4p[lane + j * 32] = make_char4(lc[0], lc[1], lc[2], lc[3]);
    }
}

// mean BCE-with-logits; single block, fixed-order -> deterministic
__global__ void bce_kernel(const float* __restrict__ y,
                           const float* __restrict__ t,
                           float* __restrict__ loss_out, int n)
{
    __shared__ float red[1024];
    float acc = 0.f;
    for (int i = threadIdx.x; i < n; i += 1024) {
        float v  = y[i];
        float tt = t[i];
        acc += fmaxf(v, 0.f) - v * tt + log1pf(__expf(-fabsf(v)));
    }
    red[threadIdx.x] = acc;
    __syncthreads();
    for (int s = 512; s > 0; s >>= 1) {
        if (threadIdx.x < s) red[threadIdx.x] += red[threadIdx.x + s];
        __syncthreads();
    }
    if (threadIdx.x == 0) loss_out[0] = red[0] / (float)n;
}

extern "C" void kernel_launch(void* const* d_in, const int* in_sizes, int n_in,
                              void* d_out, int out_size)
{
    const float* x      = (const float*)d_in[0];
    const float* target = (const float*)d_in[1];
    // d_in[2] = text_inputs (unused)
    const float* U_w    = (const float*)d_in[3];
    const float* F_w    = (const float*)d_in[4];
    const float* f_b    = (const float*)d_in[5];
    float* out = (float*)d_out;

    cudaFuncSetAttribute(attn_mma_kernel,
                         cudaFuncAttributeMaxDynamicSharedMemorySize, SMEM_BYTES);

    int8_t *uh8, *ul8, *fh8, *fl8, *xh8, *xl8;
    float *su, *sfc, *sx;
    cudaGetSymbolAddress((void**)&uh8, g_uh8);
    cudaGetSymbolAddress((void**)&ul8, g_ul8);
    cudaGetSymbolAddress((void**)&fh8, g_fh8);
    cudaGetSymbolAddress((void**)&fl8, g_fl8);
    cudaGetSymbolAddress((void**)&xh8, g_xh8);
    cudaGetSymbolAddress((void**)&xl8, g_xl8);
    cudaGetSymbolAddress((void**)&su,  g_su);
    cudaGetSymbolAddress((void**)&sfc, g_sf);
    cudaGetSymbolAddress((void**)&sx,  g_sx);

    quant_rows<<<(Yn + 7) / 8, 256>>>(U_w, uh8, ul8, su, Yn);
    quant_rows<<<(Yn + 7) / 8, 256>>>(F_w, fh8, fl8, sfc, Yn);
    quant_rows<<<(Bn * Ln + 7) / 8, 256>>>(x, xh8, xl8, sx, Bn * Ln);

    dim3 grid((Yn + YT - 1) / YT, Bn);   // 70 x 8 = 560 CTAs
    attn_mma_kernel<<<grid, NT, SMEM_BYTES>>>(f_b, out);

    if (out_size > Bn * Yn)
        bce_kernel<<<1, 1024>>>(out, target, out + Bn * Yn, Bn * Yn);
}

// round 8
// speedup vs baseline: 2.9162x; 2.9162x over previous
#include <cuda_runtime.h>
#include <cuda_bf16.h>
#include <cstdint>

#define Bn 8
#define Ln 2500
#define Dn 512
#define Yn 8921
#define YT 128          // y per CTA
#define LT 128          // l per CTA tile
#define KC 64           // k per chunk (bf16 elems)
#define NCH (Dn / KC)   // 8 chunks
#define NTILES 20       // ceil(2500/128)
#define NT 256
#define ROWB 144                    // smem row stride bytes (64 bf16 + 8 pad)
#define TILE_BYTES (128 * ROWB)     // 18432
#define BUF_BYTES (6 * TILE_BYTES)  // 110592 : Uh Ul Fh Fl Xh Xl
#define SMEM_BYTES (2 * BUF_BYTES)  // 221184

// bf16 hi/lo scratch (device globals; no runtime alloc)
__device__ __nv_bfloat16 g_xh[(size_t)Bn * Ln * Dn];
__device__ __nv_bfloat16 g_xl[(size_t)Bn * Ln * Dn];
__device__ __nv_bfloat16 g_uh[(size_t)Yn * Dn];
__device__ __nv_bfloat16 g_ul[(size_t)Yn * Dn];
__device__ __nv_bfloat16 g_fh[(size_t)Yn * Dn];
__device__ __nv_bfloat16 g_fl[(size_t)Yn * Dn];

// mma.sync m16n8k16 bf16 (plain sm_80+ instruction)
#define MMA(D, A, B0, B1)                                                   \
    asm volatile(                                                           \
        "mma.sync.aligned.m16n8k16.row.col.f32.bf16.bf16.f32 "              \
        "{%0,%1,%2,%3}, {%4,%5,%6,%7}, {%8,%9}, {%0,%1,%2,%3};"             \
        : "+f"((D)[0]), "+f"((D)[1]), "+f"((D)[2]), "+f"((D)[3])            \
        : "r"((A)[0]), "r"((A)[1]), "r"((A)[2]), "r"((A)[3]),               \
          "r"(B0), "r"(B1))

#define LDSM4(R0, R1, R2, R3, addr)                                         \
    asm volatile(                                                           \
        "ldmatrix.sync.aligned.m8n8.x4.shared.b16 {%0,%1,%2,%3}, [%4];"     \
        : "=r"(R0), "=r"(R1), "=r"(R2), "=r"(R3) : "r"(addr))

static __device__ __forceinline__ void cp16(uint32_t dst, const void* src,
                                            bool v) {
    int sz = v ? 16 : 0;   // sz=0 -> zero-fill 16B, no gmem read
    asm volatile("cp.async.cg.shared.global [%0], [%1], 16, %2;"
                 :: "r"(dst), "l"(src), "r"(sz));
}
template <int N>
static __device__ __forceinline__ void cpwait() {
    asm volatile("cp.async.wait_group %0;" :: "n"(N) : "memory");
}
static __device__ __forceinline__ uint32_t smem_u32(const void* p) {
    uint32_t a;
    asm("{ .reg .u64 t; cvta.to.shared.u64 t, %1; cvt.u32.u64 %0, t; }"
        : "=r"(a) : "l"(p));
    return a;
}

// stage one k-chunk: 6 bf16 tiles [128 rows x 64 k] -> padded smem
static __device__ __forceinline__ void stage_chunk(
    uint32_t bufaddr, int tid, int b, int y0, int l0, int k0)
{
    const __nv_bfloat16* srcs[6] = {
        g_uh + (size_t)y0 * Dn, g_ul + (size_t)y0 * Dn,
        g_fh + (size_t)y0 * Dn, g_fl + (size_t)y0 * Dn,
        g_xh + ((size_t)b * Ln + l0) * Dn,
        g_xl + ((size_t)b * Ln + l0) * Dn };
#pragma unroll
    for (int sub = 0; sub < 6; sub++) {
        const __nv_bfloat16* src = srcs[sub];
        const int lim = (sub < 4) ? (Yn - y0) : (Ln - l0);
#pragma unroll
        for (int j = 0; j < 4; j++) {
            int idx = tid + j * NT;              // 0..1023 = 128 rows x 8 segs
            int r = idx >> 3, seg = idx & 7;     // seg = 16B (8 bf16)
            cp16(bufaddr + sub * TILE_BYTES + (uint32_t)(r * ROWB + seg * 16),
                 src + (size_t)r * Dn + k0 + seg * 8, r < lim);
        }
    }
    asm volatile("cp.async.commit_group;" ::: "memory");
}

__global__ __launch_bounds__(NT)
void attn_mma_kernel(const float* __restrict__ f_b, float* __restrict__ out)
{
    extern __shared__ float smem[];
    const uint32_t sbase = smem_u32(smem);
    const int tid  = threadIdx.x;
    const int lane = tid & 31;
    const int g    = lane >> 2;          // group id 0..7
    const int tg   = lane & 3;           // thread in group 0..3
    const int wid  = tid >> 5;
    const int wy   = wid >> 1;           // warp y index 0..3 (32 y each)
    const int wl   = wid & 1;            // warp l index 0..1 (64 l each)
    const int b    = blockIdx.y;
    const int y0   = blockIdx.x * YT;

    // ldmatrix per-lane address components (bytes)
    const int quad = lane >> 3, r8 = lane & 7;
    const uint32_t laneA = (uint32_t)((r8 + (quad & 1) * 8) * ROWB + (quad >> 1) * 16);
    const uint32_t laneB = (uint32_t)((r8 + (quad >> 1) * 8) * ROWB + (quad & 1) * 16);
    uint32_t aRow[2], bRow[4];
#pragma unroll
    for (int a = 0; a < 2; a++) aRow[a] = (uint32_t)((wy * 32 + a * 16) * ROWB) + laneA;
#pragma unroll
    for (int cp = 0; cp < 4; cp++) bRow[cp] = (uint32_t)((wl * 64 + cp * 16) * ROWB) + laneB;

    // running softmax sums for this thread's 4 y rows
    float ss[4] = {0.f, 0.f, 0.f, 0.f};
    float zz[4] = {0.f, 0.f, 0.f, 0.f};

    stage_chunk(sbase, tid, b, y0, 0, 0);   // tile 0, chunk 0 -> buf 0

    for (int t = 0; t < NTILES; t++) {
        const int l0 = t * LT;

        float dS[2][8][4], dT[2][8][4];
#pragma unroll
        for (int a = 0; a < 2; a++)
#pragma unroll
            for (int c = 0; c < 8; c++)
#pragma unroll
                for (int r = 0; r < 4; r++) { dS[a][c][r] = 0.f; dT[a][c][r] = 0.f; }

        for (int ch = 0; ch < NCH; ch++) {
            // current chunk's stage is the only in-flight group: drain it
            cpwait<0>();
            __syncthreads();   // all warps done with the OTHER buffer too

            const bool last_all = (t == NTILES - 1) && (ch == NCH - 1);
            if (!last_all) {
                // prefetch next chunk (possibly next tile's chunk 0);
                // overlaps with this chunk's mma block
                int nl0 = (ch == NCH - 1) ? l0 + LT : l0;
                int nk0 = (ch == NCH - 1) ? 0 : (ch + 1) * KC;
                stage_chunk(sbase + ((ch + 1) & 1) * BUF_BYTES, tid, b, y0, nl0, nk0);
            }

            const uint32_t bufb = sbase + (ch & 1) * BUF_BYTES;

#pragma unroll
            for (int ka = 0; ka < 4; ka++) {        // four k16 steps
                const uint32_t kao = (uint32_t)(ka * 32);
                uint32_t auh[2][4], aul[2][4], afh[2][4], afl[2][4];
#pragma unroll
                for (int a = 0; a < 2; a++) {
                    uint32_t ab = bufb + aRow[a] + kao;
                    LDSM4(auh[a][0], auh[a][1], auh[a][2], auh[a][3], ab);
                    LDSM4(aul[a][0], aul[a][1], aul[a][2], aul[a][3], ab + TILE_BYTES);
                    LDSM4(afh[a][0], afh[a][1], afh[a][2], afh[a][3], ab + 2 * TILE_BYTES);
                    LDSM4(afl[a][0], afl[a][1], afl[a][2], afl[a][3], ab + 3 * TILE_BYTES);
                }
                uint32_t bh[8][2], bl[8][2];
#pragma unroll
                for (int cp = 0; cp < 4; cp++) {
                    uint32_t bb = bufb + 4 * TILE_BYTES + bRow[cp] + kao;
                    LDSM4(bh[2*cp][0], bh[2*cp][1], bh[2*cp+1][0], bh[2*cp+1][1], bb);
                    LDSM4(bl[2*cp][0], bl[2*cp][1], bl[2*cp+1][0], bl[2*cp+1][1],
                          bb + TILE_BYTES);
                }
                // term-major ordering: same-accumulator reuse distance = 32 mma
                // (was 1 — three chained HMMAs on one D caused RAW stalls)
#pragma unroll
                for (int a = 0; a < 2; a++)
#pragma unroll
                    for (int c = 0; c < 8; c++) MMA(dS[a][c], auh[a], bh[c][0], bh[c][1]);
#pragma unroll
                for (int a = 0; a < 2; a++)
#pragma unroll
                    for (int c = 0; c < 8; c++) MMA(dT[a][c], afh[a], bh[c][0], bh[c][1]);
#pragma unroll
                for (int a = 0; a < 2; a++)
#pragma unroll
                    for (int c = 0; c < 8; c++) MMA(dS[a][c], auh[a], bl[c][0], bl[c][1]);
#pragma unroll
                for (int a = 0; a < 2; a++)
#pragma unroll
                    for (int c = 0; c < 8; c++) MMA(dT[a][c], afh[a], bl[c][0], bl[c][1]);
#pragma unroll
                for (int a = 0; a < 2; a++)
#pragma unroll
                    for (int c = 0; c < 8; c++) MMA(dS[a][c], aul[a], bh[c][0], bh[c][1]);
#pragma unroll
                for (int a = 0; a < 2; a++)
#pragma unroll
                    for (int c = 0; c < 8; c++) MMA(dT[a][c], afl[a], bh[c][0], bh[c][1]);
            }
        }

        // epilogue (regs only) — overlaps the in-flight prefetch of next tile
#pragma unroll
        for (int a = 0; a < 2; a++)
#pragma unroll
            for (int c = 0; c < 8; c++)
#pragma unroll
                for (int r2 = 0; r2 < 2; r2++) {
                    int le = l0 + wl * 64 + c * 8 + 2 * tg;
                    float s0 = dS[a][c][r2 * 2],     t0 = dT[a][c][r2 * 2];
                    float s1 = dS[a][c][r2 * 2 + 1], t1 = dT[a][c][r2 * 2 + 1];
                    if (le < Ln)     { float e = __expf(s0); ss[a*2+r2] += e; zz[a*2+r2] += e * t0; }
                    if (le + 1 < Ln) { float e = __expf(s1); ss[a*2+r2] += e; zz[a*2+r2] += e * t1; }
                }
    }

    // reduce across the 4 lanes sharing each y row (tg dimension)
#pragma unroll
    for (int i = 0; i < 4; i++) {
        ss[i] += __shfl_xor_sync(0xffffffffu, ss[i], 1);
        ss[i] += __shfl_xor_sync(0xffffffffu, ss[i], 2);
        zz[i] += __shfl_xor_sync(0xffffffffu, zz[i], 1);
        zz[i] += __shfl_xor_sync(0xffffffffu, zz[i], 2);
    }

    // cross-warp (wl) reduction via smem (all staging finished by now)
    __syncthreads();
    float* sred = smem;          // [2][128]
    float* zred = smem + 256;    // [2][128]
    if (tg == 0) {
#pragma unroll
        for (int i = 0; i < 4; i++) {
            int yl = wy * 32 + (i >> 1) * 16 + (i & 1) * 8 + g;
            sred[wl * 128 + yl] = ss[i];
            zred[wl * 128 + yl] = zz[i];
        }
    }
    __syncthreads();
    if (tid < 128) {
        int yg = y0 + tid;
        if (yg < Yn) {
            float s = sred[tid] + sred[128 + tid];
            float z = zred[tid] + zred[128 + tid];
            out[(size_t)b * Yn + yg] = z / s + f_b[yg];
        }
    }
}

// ---------------- prepass: fp32 -> bf16 hi/lo ----------------
static __device__ __forceinline__ void split2(float v, __nv_bfloat16* h,
                                              __nv_bfloat16* l) {
    __nv_bfloat16 hh = __float2bfloat16(v);
    *h = hh;
    *l = __float2bfloat16(v - __bfloat162float(hh));
}

__global__ void prep_w(const float* __restrict__ U, const float* __restrict__ F)
{
    const size_t n = (size_t)Yn * Dn;
    for (size_t i = (size_t)blockIdx.x * blockDim.x + threadIdx.x; i < n;
         i += (size_t)gridDim.x * blockDim.x) {
        split2(U[i], &g_uh[i], &g_ul[i]);
        split2(F[i], &g_fh[i], &g_fl[i]);
    }
}

__global__ void prep_x(const float* __restrict__ x)
{
    const size_t n = (size_t)Bn * Ln * Dn;
    for (size_t i = (size_t)blockIdx.x * blockDim.x + threadIdx.x; i < n;
         i += (size_t)gridDim.x * blockDim.x)
        split2(x[i], &g_xh[i], &g_xl[i]);
}

// mean BCE-with-logits; single block, fixed-order -> deterministic
__global__ void bce_kernel(const float* __restrict__ y,
                           const float* __restrict__ t,
                           float* __restrict__ loss_out, int n)
{
    __shared__ float red[1024];
    float acc = 0.f;
    for (int i = threadIdx.x; i < n; i += 1024) {
        float v  = y[i];
        float tt = t[i];
        acc += fmaxf(v, 0.f) - v * tt + log1pf(__expf(-fabsf(v)));
    }
    red[threadIdx.x] = acc;
    __syncthreads();
    for (int s = 512; s > 0; s >>= 1) {
        if (threadIdx.x < s) red[threadIdx.x] += red[threadIdx.x + s];
        __syncthreads();
    }
    if (threadIdx.x == 0) loss_out[0] = red[0] / (float)n;
}

extern "C" void kernel_launch(void* const* d_in, const int* in_sizes, int n_in,
                              void* d_out, int out_size)
{
    const float* x      = (const float*)d_in[0];
    const float* target = (const float*)d_in[1];
    // d_in[2] = text_inputs (unused)
    const float* U_w    = (const float*)d_in[3];
    const float* F_w    = (const float*)d_in[4];
    const float* f_b    = (const float*)d_in[5];
    float* out = (float*)d_out;

    cudaFuncSetAttribute(attn_mma_kernel,
                         cudaFuncAttributeMaxDynamicSharedMemorySize, SMEM_BYTES);

    prep_w<<<1024, 256>>>(U_w, F_w);
    prep_x<<<2048, 256>>>(x);

    dim3 grid((Yn + YT - 1) / YT, Bn);   // 70 x 8 = 560 CTAs
    attn_mma_kernel<<<grid, NT, SMEM_BYTES>>>(f_b, out);

    if (out_size > Bn * Yn)
        bce_kernel<<<1, 1024>>>(out, target, out + Bn * Yn, Bn * Yn);
}